// round 5
// baseline (speedup 1.0000x reference)
#include <cuda_runtime.h>
#include <math.h>

#define D       256
#define NA      360
#define SR      16                      // strip rows
#define NS      (D / SR)                // 16 strips
#define STRIPF4 ((SR + 1) * D)          // 4352 float4 per strip buffer (17 rows)
#define NTH     512
#define SMEM_BYTES (2 * STRIPF4 * (int)sizeof(float4))   // 139264

// Pixel-major 4-batch-packed image copies.
// g_imgA[g][y*256+x], g_imgB[g][x*256+y]; g selects batches 4g..4g+3.
__device__ float4 g_imgA[2][D * D];
__device__ float4 g_imgB[2][D * D];
__device__ float2 g_cs[NA];             // (cos, sin) per angle, computed in fp64

__global__ void radon_prep(const float* __restrict__ x) {
    int i = blockIdx.x * blockDim.x + threadIdx.x;
    if (i < NA) {
        double t = (double)i * (M_PI / 360.0);   // i * 0.5 deg in radians
        g_cs[i] = make_float2((float)cos(t), (float)sin(t));
    }
    if (i >= 2 * D * D) return;
    int g   = i >> 16;
    int pix = i & (D * D - 1);
    int yy  = pix >> 8;
    int xx  = pix & (D - 1);
    const float* p = x + (size_t)g * 4 * D * D + pix;
    float4 v = make_float4(p[0], p[D * D], p[2 * D * D], p[3 * D * D]);
    g_imgA[g][pix] = v;
    g_imgB[g][xx * D + yy] = v;
}

__device__ __forceinline__ void strip_prefetch(const float4* __restrict__ base,
                                               float4* buf, int k, int tid) {
    int row0 = k * SR;
    for (int idx = tid; idx < STRIPF4; idx += NTH) {
        int rr = idx >> 8;
        int cc = idx & (D - 1);
        int gr = min(row0 + rr, D - 1);          // strip 15 row 16 duplicates row 255 (weight 0)
        const float4* src = base + gr * D + cc;
        unsigned int daddr = (unsigned int)__cvta_generic_to_shared(buf + idx);
        asm volatile("cp.async.cg.shared.global [%0], [%1], 16;" :: "r"(daddr), "l"(src));
    }
}

// CTA = (angle a, batch-group g). Thread (w, half); half splits each h-range.
// Coordinates (pixel units, u = w-127.5, v = h-127.5):
//   ix = c*u - s*v + 127.5 ; iy = s*u + c*v + 127.5
// mode0 (|c| >= s): strip over iy, smem y-major.  r = iy, p = ix.
// mode1 (s > |c|) : strip over ix, smem x-major.  r = ix, p = iy.
// In both modes |dr/dh| >= 0.707.
__global__ void __launch_bounds__(NTH, 1) radon_main(float* __restrict__ out) {
    extern __shared__ float4 sm[];
    const int a    = blockIdx.x;
    const int g    = blockIdx.y;
    const int tid  = threadIdx.x;
    const int w    = tid & (D - 1);
    const int half = tid >> 8;

    float2 cs = g_cs[a];
    float c = cs.x, s = cs.y;
    bool mode0 = fabsf(c) >= s;
    float r_u = mode0 ? s : c;
    float r_v = mode0 ? c : -s;
    float p_u = mode0 ? c : s;
    float p_v = mode0 ? -s : c;
    const float4* __restrict__ base = mode0 ? g_imgA[g] : g_imgB[g];

    float u    = (float)w - 127.5f;
    float A    = r_v;                                    // |A| >= 0.707
    float Bc   = fmaf(r_u, u, 127.5f * (1.0f - r_v));    // r(h) = A*h + Bc
    float Ap   = p_v;
    float Bp   = fmaf(p_u, u, 127.5f * (1.0f - p_v));    // p(h) = Ap*h + Bp
    float invA = 1.0f / A;

    float ax = 0.0f, ay = 0.0f, az = 0.0f, aw = 0.0f;

    strip_prefetch(base, sm, 0, tid);
    asm volatile("cp.async.commit_group;");

    for (int k = 0; k < NS; k++) {
        if (k + 1 < NS) {
            strip_prefetch(base, sm + ((k + 1) & 1) * STRIPF4, k + 1, tid);
            asm volatile("cp.async.commit_group;");
            asm volatile("cp.async.wait_group 1;");
        } else {
            asm volatile("cp.async.wait_group 0;");
        }
        __syncthreads();
        const float4* __restrict__ S = sm + (k & 1) * STRIPF4;

        const int lo    = k * SR;
        const int hi    = lo + SR - 1;
        const int loOwn = (k == 0) ? -1 : lo;   // strip 0 also owns floor(r) == -1

        // Widened h-range for floor(r) in [loOwn, hi]  <=>  r in [loOwn, hi+1)
        float e0 = ((float)loOwn    - Bc) * invA;
        float e1 = ((float)(hi + 1) - Bc) * invA;
        float emin = fminf(e0, e1);
        float emax = fmaxf(e0, e1);
        int hbeg = max(0,     (int)floorf(emin) - 1);
        int hend = min(D - 1, (int)floorf(emax) + 1);
        int cnt  = max(0, hend - hbeg + 1);
        int ch   = (cnt + 1) >> 1;
        int ib   = half ? ch  : 0;
        int ie   = half ? cnt : ch;

        for (int i = ib; i < ie; i++) {
            float fh = (float)(hbeg + i);
            float r  = fmaf(A,  fh, Bc);
            float p  = fmaf(Ap, fh, Bp);
            float rf = floorf(r);
            float pf = floorf(p);
            int sr = (int)rf;
            int sp = (int)pf;
            // exact ownership (no double count across strips) + p fully outside skip
            if (sr < loOwn || sr > hi || sp < -1 || sp > D - 1) continue;
            float wr1 = r - rf, wr0 = 1.0f - wr1;
            float wp1 = p - pf, wp0 = 1.0f - wp1;
            float mr0 = (sr >= 0)     ? wr0 : 0.0f;
            float mr1 = (sr <= D - 2) ? wr1 : 0.0f;
            float mp0 = (sp >= 0)     ? wp0 : 0.0f;
            float mp1 = (sp <= D - 2) ? wp1 : 0.0f;
            int pc0 = max(sp, 0);               // sp <= 255 guaranteed
            int pc1 = min(sp + 1, D - 1);       // sp+1 >= 0 guaranteed
            int ry  = sr - lo;                  // -1..15
            int r0i = max(ry, 0) * D;
            int r1i = (ry + 1) * D;             // 0..16, row 16 exists (17-row buffer)
            float4 v00 = S[r0i + pc0];
            float4 v01 = S[r0i + pc1];
            float4 v10 = S[r1i + pc0];
            float4 v11 = S[r1i + pc1];
            float w00 = mr0 * mp0, w01 = mr0 * mp1;
            float w10 = mr1 * mp0, w11 = mr1 * mp1;
            ax += w00 * v00.x + w01 * v01.x + w10 * v10.x + w11 * v11.x;
            ay += w00 * v00.y + w01 * v01.y + w10 * v10.y + w11 * v11.y;
            az += w00 * v00.z + w01 * v01.z + w10 * v10.z + w11 * v11.z;
            aw += w00 * v00.w + w01 * v01.w + w10 * v10.w + w11 * v11.w;
        }
        __syncthreads();
    }

    // reduce the two halves, write output (mean over h = sum/256)
    if (half == 1) sm[w] = make_float4(ax, ay, az, aw);
    __syncthreads();
    if (half == 0) {
        float4 o = sm[w];
        ax += o.x; ay += o.y; az += o.z; aw += o.w;
        const float sc = 1.0f / 256.0f;
        int b0 = g * 4;
        out[((b0 + 0) * NA + a) * D + w] = ax * sc;
        out[((b0 + 1) * NA + a) * D + w] = ay * sc;
        out[((b0 + 2) * NA + a) * D + w] = az * sc;
        out[((b0 + 3) * NA + a) * D + w] = aw * sc;
    }
}

extern "C" void kernel_launch(void* const* d_in, const int* in_sizes, int n_in,
                              void* d_out, int out_size) {
    const float* x = (const float*)d_in[0];
    float* out = (float*)d_out;
    cudaFuncSetAttribute(radon_main, cudaFuncAttributeMaxDynamicSharedMemorySize, SMEM_BYTES);
    radon_prep<<<(2 * D * D + NTH - 1) / NTH, NTH>>>(x);
    radon_main<<<dim3(NA, 2), NTH, SMEM_BYTES>>>(out);
}